// round 2
// baseline (speedup 1.0000x reference)
#include <cuda_runtime.h>

// AllZeroDigitalFilter: time-varying FIR, 50 taps, frame period 80.
// y[b,t] = sum_{j=0..49} x[b, t+j-49] * h[b,t,j]
// h[t=n*80+p][j] = (1-p/80)*bf[n][j] + (p/80)*bf[min(n+1,N-1)][j],  bf[n][j] = b[n][49-j]
// Split: y = acc0 + w*acc1 with acc0 = sum x*cL, acc1 = sum x*(cR-cL); cL,cD frame-constant.

#define TAPS       50
#define FP         80          // frame period
#define FPB        20          // frames per block
#define THREADS    200         // 10 threads per frame
#define KOUT       8           // outputs per thread (8*10 = 80 = FP)
#define OUT_PB     (FPB * FP)  // 1600 outputs per block
#define XWIN       1650        // x window loaded: [t0-49, t0+1601)
#define XPAD(i)    ((i) + ((i) >> 3))   // stride-9 padding: kills 8-way bank conflicts

__global__ __launch_bounds__(THREADS, 8)
void azdf_kernel(const float* __restrict__ x,
                 const float* __restrict__ b,
                 float* __restrict__ y,
                 int T, int Nf)
{
    __shared__ float sx[XPAD(XWIN - 1) + 2];   // padded x window
    __shared__ float sL[FPB * TAPS];           // cL  (flipped left-frame coeffs)
    __shared__ float sD[FPB * TAPS];           // cR - cL

    const int bb = blockIdx.y;
    const int n0 = blockIdx.x * FPB;
    const int t0 = n0 * FP;

    const float* xb  = x + (long long)bb * T;
    const float* bbp = b + (long long)bb * Nf * TAPS;

    // ---- stage x window into padded shared ----
    for (int i = threadIdx.x; i < XWIN; i += THREADS) {
        int g = t0 - (TAPS - 1) + i;
        float v = (g >= 0 && g < T) ? xb[g] : 0.0f;
        sx[XPAD(i)] = v;
    }

    // ---- stage coefficients: flip + diff ----
    for (int idx = threadIdx.x; idx < FPB * TAPS; idx += THREADS) {
        int r = idx / TAPS;
        int j = idx - r * TAPS;
        int n  = n0 + r;
        int n1 = min(n + 1, Nf - 1);
        float l  = bbp[n  * TAPS + (TAPS - 1 - j)];
        float rr = bbp[n1 * TAPS + (TAPS - 1 - j)];
        sL[idx] = l;
        sD[idx] = rr - l;
    }
    __syncthreads();

    // ---- per-thread: 8 consecutive outputs within one frame ----
    const int f  = threadIdx.x / 10;          // frame within block
    const int q  = threadIdx.x - f * 10;      // 8-output group within frame
    const int lt = f * FP + q * KOUT;         // == 8 * threadIdx.x

    const float* cL = sL + f * TAPS;
    const float* cD = sD + f * TAPS;

    float xw[KOUT];
    float a0[KOUT], a1[KOUT];
    #pragma unroll
    for (int k = 0; k < KOUT; ++k) {
        a0[k] = 0.0f; a1[k] = 0.0f;
        int i = lt + k;
        xw[k] = sx[XPAD(i)];
    }

    #pragma unroll 10
    for (int j = 0; j < TAPS; ++j) {
        float cl = cL[j];
        float dd = cD[j];
        #pragma unroll
        for (int k = 0; k < KOUT; ++k) {
            a0[k] = fmaf(xw[k], cl, a0[k]);
            a1[k] = fmaf(xw[k], dd, a1[k]);
        }
        #pragma unroll
        for (int k = 0; k < KOUT - 1; ++k) xw[k] = xw[k + 1];
        int i = lt + j + KOUT;                 // next sample (max 1649 < XWIN)
        xw[KOUT - 1] = sx[XPAD(i)];
    }

    // ---- interpolate + coalesced vector store ----
    float out[KOUT];
    #pragma unroll
    for (int k = 0; k < KOUT; ++k) {
        float w = (float)(q * KOUT + k) / (float)FP;
        out[k] = fmaf(w, a1[k], a0[k]);
    }
    float4* yp = (float4*)(y + (long long)bb * T + t0 + lt);
    yp[0] = make_float4(out[0], out[1], out[2], out[3]);
    yp[1] = make_float4(out[4], out[5], out[6], out[7]);
}

extern "C" void kernel_launch(void* const* d_in, const int* in_sizes, int n_in,
                              void* d_out, int out_size)
{
    const float* x = (const float*)d_in[0];   // (B, T) float32
    const float* b = (const float*)d_in[1];   // (B, N, 50) float32
    float* y = (float*)d_out;                 // (B, T) float32

    const int Nf = 3000;
    const int T  = Nf * FP;                   // 240000
    const int B  = in_sizes[0] / T;           // 8

    dim3 grid(Nf / FPB, B);                   // (150, 8)
    azdf_kernel<<<grid, THREADS>>>(x, b, y, T, Nf);
}